// round 9
// baseline (speedup 1.0000x reference)
#include <cuda_runtime.h>
#include <cstddef>
#include <cstdint>

#define T_STEPS 2048
#define BATCH   64
#define ZLD     1032         // 4*256 + 8
#define QSTR    0.5f
#define CL      8            // CTAs per cluster (portable size)
#define ROWS    4            // batch rows per cluster/group
#define UPC     32           // units per CTA (8 * 32 = 256)

// ---------------- scratch (static device global; no allocation) -------------
__device__ float g_Z[(size_t)T_STEPS * BATCH * ZLD];   // x-projection + bias

// ---------------------------------------------------------------------------
// Kernel 1: Z = X @ Wx + bias. 128m x 128n tiles, 256 threads, 8x8 microtile.
// ---------------------------------------------------------------------------
__global__ void __launch_bounds__(256)
xproj_kernel(const float* __restrict__ X,
             const float* __restrict__ Wf, const float* __restrict__ bf,
             const float* __restrict__ Wi, const float* __restrict__ bi,
             const float* __restrict__ Wg, const float* __restrict__ bg,
             const float* __restrict__ Wo, const float* __restrict__ bo,
             const float* __restrict__ Wq, const float* __restrict__ bq)
{
    __shared__ float Xs[8][132];   // [k][m]
    __shared__ float Bs[8][132];   // [k][n]

    const int row0 = blockIdx.x * 128;
    const int nt   = blockIdx.y;          // 0..8

    const float* W; const float* bias; int ld, wc0, col0, nvalid;
    if (nt < 8) {
        int gate = nt >> 1;
        W    = (gate == 0) ? Wf : (gate == 1) ? Wi : (gate == 2) ? Wg : Wo;
        bias = (gate == 0) ? bf : (gate == 1) ? bi : (gate == 2) ? bg : bo;
        ld = 256; wc0 = (nt & 1) * 128; col0 = nt * 128; nvalid = 128;
    } else {
        W = Wq; bias = bq; ld = 8; wc0 = 0; col0 = 1024; nvalid = 8;
    }

    const int tid = threadIdx.x;          // 256
    const int tx  = tid & 15;
    const int ty  = tid >> 4;

    float acc[8][8] = {};

    for (int k0 = 0; k0 < 256; k0 += 8) {
        {
            int m = tid >> 1, kq = tid & 1;
            float4 v = *(const float4*)(X + (size_t)(row0 + m) * 256 + k0 + kq * 4);
            Xs[kq * 4 + 0][m] = v.x;
            Xs[kq * 4 + 1][m] = v.y;
            Xs[kq * 4 + 2][m] = v.z;
            Xs[kq * 4 + 3][m] = v.w;
        }
        {
            int k = tid >> 5, n4 = tid & 31;
            float4 w4 = { 0.f, 0.f, 0.f, 0.f };
            if (n4 * 4 < nvalid)
                w4 = *(const float4*)(W + (size_t)(k0 + k) * ld + wc0 + n4 * 4);
            *(float4*)&Bs[k][n4 * 4] = w4;
        }
        __syncthreads();

        #pragma unroll
        for (int kk = 0; kk < 8; kk++) {
            float4 a0 = *(const float4*)&Xs[kk][ty * 4];
            float4 a1 = *(const float4*)&Xs[kk][64 + ty * 4];
            float4 b0 = *(const float4*)&Bs[kk][tx * 4];
            float4 b1 = *(const float4*)&Bs[kk][64 + tx * 4];
            float a[8] = { a0.x, a0.y, a0.z, a0.w, a1.x, a1.y, a1.z, a1.w };
            float b[8] = { b0.x, b0.y, b0.z, b0.w, b1.x, b1.y, b1.z, b1.w };
            #pragma unroll
            for (int i = 0; i < 8; i++)
                #pragma unroll
                for (int j = 0; j < 8; j++)
                    acc[i][j] += a[i] * b[j];
        }
        __syncthreads();
    }

    #pragma unroll
    for (int i = 0; i < 8; i++) {
        int r = row0 + ((i < 4) ? (ty * 4 + i) : (64 + ty * 4 + i - 4));
        #pragma unroll
        for (int j = 0; j < 8; j++) {
            int n = (j < 4) ? (tx * 4 + j) : (64 + tx * 4 + j - 4);
            if (n < nvalid)
                g_Z[(size_t)r * ZLD + col0 + n] = acc[i][j] + bias[wc0 + n];
        }
    }
}

// ---------------------------------------------------------------------------
// packed fp32x2 helpers
// ---------------------------------------------------------------------------
__device__ __forceinline__ unsigned long long pack2(float a, float b) {
    unsigned long long r;
    asm("mov.b64 %0, {%1, %2};" : "=l"(r) : "f"(a), "f"(b));
    return r;
}
__device__ __forceinline__ void unpack2(unsigned long long v, float& a, float& b) {
    asm("mov.b64 {%0, %1}, %2;" : "=f"(a), "=f"(b) : "l"(v));
}
__device__ __forceinline__ void fma2(unsigned long long& d,
                                     unsigned long long a, unsigned long long b) {
    asm("fma.rn.f32x2 %0, %1, %2, %0;" : "+l"(d) : "l"(a), "l"(b));
}
__device__ __forceinline__ float sigmoidf_(float x) {
    return 1.f / (1.f + __expf(-x));
}

// ---------------------------------------------------------------------------
// Kernel 2: clustered persistent recurrence.
// Grid 128 = 16 groups x 8-CTA portable clusters, 512 threads.
// Group owns 4 batch rows; CTA owns 32 units. warp = (kch 0..3, uu_hi 0..3);
// lane = (kcl 0..3, uu_low 0..7). Weights in registers. hx double-buffered in
// smem, filled via st.shared::cluster.v4. One barrier.cluster per step.
// Rows processed one at a time to bound register pressure.
// ---------------------------------------------------------------------------
__global__ void __launch_bounds__(512, 1) __cluster_dims__(CL, 1, 1)
lstm_cluster(const float* __restrict__ Wf,
             const float* __restrict__ Wi,
             const float* __restrict__ Wg,
             const float* __restrict__ Wo,
             const float* __restrict__ Wq,
             float* __restrict__ stacked,   // [T,B,256]
             float* __restrict__ hx_out,    // [B,256]
             float* __restrict__ cx_out)    // [B,256]
{
    __shared__ float sm_h[2 * ROWS * 264];      // double-buffered hx tile
    __shared__ float sm_red[16 * 8 * 21];       // [warp][uu_low][row*5 (+1 pad)]
    __shared__ float sm_stage[ROWS * 36];       // h staging, padded

    const int tid  = threadIdx.x;  // 512
    const int warp = tid >> 5;
    const int lane = tid & 31;

    uint32_t rank;
    asm("mov.u32 %0, %%cluster_ctarank;" : "=r"(rank));
    const int grp = blockIdx.x >> 3;            // 0..15
    const int b0  = grp * ROWS;
    const int u0  = (int)rank * UPC;

    const int uu_low = lane & 7;
    const int kcl    = lane >> 3;               // 0..3
    const int kch    = warp & 3;                // 0..3
    const int uu_hi  = warp >> 2;               // 0..3
    const int uu     = uu_hi * 8 + uu_low;      // 0..31
    const int k0     = (kch * 4 + kcl) * 16;    // 16-k chunk base

    // ---- weights in registers: 5 gates x 8 k-pairs (q zero for uu>=8) ----
    unsigned long long wv[5][8];
    {
        const float* Wp[4] = { Wf, Wi, Wg, Wo };
        #pragma unroll
        for (int g = 0; g < 4; g++)
            #pragma unroll
            for (int kp = 0; kp < 8; kp++) {
                int k = 256 + k0 + 2 * kp;
                wv[g][kp] = pack2(Wp[g][(size_t)k * 256 + u0 + uu],
                                  Wp[g][(size_t)(k + 1) * 256 + u0 + uu]);
            }
        #pragma unroll
        for (int kp = 0; kp < 8; kp++) {
            int k = 256 + k0 + 2 * kp;
            wv[4][kp] = (uu < 8)
                ? pack2(Wq[(size_t)k * 8 + uu], Wq[(size_t)(k + 1) * 8 + uu])
                : 0ull;
        }
    }

    // ---- zero read-buffer 0 (buffer 1 is written by step 0's broadcast) ----
    for (int i = tid; i < ROWS * 264; i += 512) sm_h[i] = 0.f;
    __syncthreads();
    // all CTAs initialized before any peer DSMEM traffic
    asm volatile("barrier.cluster.arrive.aligned;" ::: "memory");
    asm volatile("barrier.cluster.wait.aligned;"   ::: "memory");

    // ---- owner mapping: tid < 128; warp = row, lane = unit ----
    const bool own   = (tid < 128);
    const int  o_row = warp;                    // 0..3 when own
    const int  o_uu  = lane;                    // 0..31
    const int  ob    = b0 + o_row;
    const int  oug   = u0 + o_uu;
    const float* o_z = g_Z + (size_t)ob * ZLD;
    float c = 0.f, h = 0.f;

    for (int t = 0; t < T_STEPS; t++) {
        const float* hb = sm_h + (t & 1) * (ROWS * 264);   // read buffer

        // prefetch Z early
        float zF = 0.f, zI = 0.f, zG = 0.f, zO = 0.f, zQ = 0.f;
        if (own) {
            const float* z = o_z + (size_t)t * (BATCH * ZLD);
            zF = __ldg(z + oug);
            zI = __ldg(z + 256 + oug);
            zG = __ldg(z + 512 + oug);
            zO = __ldg(z + 768 + oug);
            zQ = (o_uu < 8) ? __ldg(z + 1024 + o_uu) : 0.f;
        }

        // ---- one row at a time: dots + in-warp reduce + sm_red write ----
        #pragma unroll
        for (int j = 0; j < ROWS; j++) {
            const float* hr = hb + j * 264 + k0;
            float4 a = *(const float4*)hr;
            float4 b = *(const float4*)(hr + 4);
            float4 d = *(const float4*)(hr + 8);
            float4 e = *(const float4*)(hr + 12);
            unsigned long long hk[8] = {
                pack2(a.x, a.y), pack2(a.z, a.w),
                pack2(b.x, b.y), pack2(b.z, b.w),
                pack2(d.x, d.y), pack2(d.z, d.w),
                pack2(e.x, e.y), pack2(e.z, e.w)
            };
            unsigned long long acc[5] = { 0ull, 0ull, 0ull, 0ull, 0ull };
            #pragma unroll
            for (int g = 0; g < 5; g++)
                #pragma unroll
                for (int kp = 0; kp < 8; kp++)
                    fma2(acc[g], hk[kp], wv[g][kp]);

            float v[5];
            #pragma unroll
            for (int g = 0; g < 5; g++) {
                float lo, hi;
                unpack2(acc[g], lo, hi);
                v[g] = lo + hi;
            }
            #pragma unroll
            for (int g = 0; g < 5; g++) {
                v[g] += __shfl_xor_sync(0xffffffffu, v[g], 8);
                v[g] += __shfl_xor_sync(0xffffffffu, v[g], 16);
            }
            if (kcl == 0) {
                float* dst = sm_red + (warp * 8 + uu_low) * 21 + j * 5;
                #pragma unroll
                for (int g = 0; g < 5; g++) dst[g] = v[g];
            }
        }
        __syncthreads();

        // ---- owners finalize ----
        if (own) {
            float aF = zF, aI = zI, aG = zG, aO = zO, aQ = zQ;
            const int ug = (o_uu >> 3);         // uu_hi of this unit
            const int ul = (o_uu & 7);
            #pragma unroll
            for (int w = 0; w < 4; w++) {       // kch partials live in warps ug*4+w
                const float* src = sm_red + ((ug * 4 + w) * 8 + ul) * 21 + o_row * 5;
                aF += src[0]; aI += src[1]; aG += src[2]; aO += src[3]; aQ += src[4];
            }

            float s = (o_uu < 8) ? tanhf(aQ) : 0.f;
            s += __shfl_xor_sync(0xffffffffu, s, 1);
            s += __shfl_xor_sync(0xffffffffu, s, 2);
            s += __shfl_xor_sync(0xffffffffu, s, 4);
            const float qout = sigmoidf_(__shfl_sync(0xffffffffu, s, 0));

            const float f = (1.f - QSTR) * sigmoidf_(aF) + QSTR * qout;
            const float i = sigmoidf_(aI);
            const float g = tanhf(aG);
            const float o = sigmoidf_(aO);

            c = f * c + i * g;
            h = o * tanhf(c);

            __stcg(stacked + ((size_t)t * BATCH + ob) * 256 + oug, h);

            // stage h (warp-local), then broadcast float4 chunks to all ranks
            sm_stage[o_row * 36 + o_uu] = h;
            __syncwarp();

            const int chunk = lane & 7;         // 8 chunks of 4 floats
            const int r0    = lane >> 3;        // this lane serves ranks r0, r0+4
            float4 hv = *(const float4*)(sm_stage + o_row * 36 + chunk * 4);
            const int woff = ((t + 1) & 1) * (ROWS * 264) + o_row * 264
                           + u0 + chunk * 4;
            uint32_t la = (uint32_t)__cvta_generic_to_shared(sm_h + woff);
            uint32_t ra;
            asm("mapa.shared::cluster.u32 %0, %1, %2;" : "=r"(ra) : "r"(la), "r"(r0));
            asm volatile("st.shared::cluster.v4.f32 [%0], {%1,%2,%3,%4};"
                         :: "r"(ra), "f"(hv.x), "f"(hv.y), "f"(hv.z), "f"(hv.w));
            asm("mapa.shared::cluster.u32 %0, %1, %2;" : "=r"(ra) : "r"(la), "r"(r0 + 4));
            asm volatile("st.shared::cluster.v4.f32 [%0], {%1,%2,%3,%4};"
                         :: "r"(ra), "f"(hv.x), "f"(hv.y), "f"(hv.z), "f"(hv.w));
        }

        // one cluster barrier per step (release/acquire orders DSMEM + smem)
        asm volatile("barrier.cluster.arrive.aligned;" ::: "memory");
        asm volatile("barrier.cluster.wait.aligned;"   ::: "memory");
    }

    if (own) {
        hx_out[ob * 256 + oug] = h;
        cx_out[ob * 256 + oug] = c;
    }
}

// ---------------------------------------------------------------------------
extern "C" void kernel_launch(void* const* d_in, const int* in_sizes, int n_in,
                              void* d_out, int out_size)
{
    const float* X  = (const float*)d_in[0];
    const float* Wf = (const float*)d_in[1];
    const float* bf = (const float*)d_in[2];
    const float* Wi = (const float*)d_in[3];
    const float* bi = (const float*)d_in[4];
    const float* Wg = (const float*)d_in[5];
    const float* bg = (const float*)d_in[6];
    const float* Wo = (const float*)d_in[7];
    const float* bo = (const float*)d_in[8];
    const float* Wq = (const float*)d_in[9];
    const float* bq = (const float*)d_in[10];

    float* out     = (float*)d_out;
    float* stacked = out;                                  // [T,B,256]
    float* hx_out  = out + (size_t)T_STEPS * BATCH * 256;  // [B,256]
    float* cx_out  = hx_out + BATCH * 256;                 // [B,256]

    // 1) precompute input projections
    dim3 g1(T_STEPS * BATCH / 128, 9);
    xproj_kernel<<<g1, 256>>>(X, Wf, bf, Wi, bi, Wg, bg, Wo, bo, Wq, bq);

    // 2) clustered persistent recurrence (portable 8-CTA clusters)
    lstm_cluster<<<16 * CL, 512>>>(Wf, Wi, Wg, Wo, Wq, stacked, hx_out, cx_out);
}

// round 10
// speedup vs baseline: 1.0595x; 1.0595x over previous
#include <cuda_runtime.h>
#include <cstddef>
#include <cstdint>

#define T_STEPS 2048
#define BATCH   64
#define ZLD     1032         // 4*256 + 8
#define QSTR    0.5f

// ---------------- scratch (static device globals; no allocation) ------------
__device__ float g_Z[(size_t)T_STEPS * BATCH * ZLD];    // x-projection + bias
__device__ unsigned long long g_htag[2][BATCH][256];    // (tag,h) packets, 256KB

// ---------------------------------------------------------------------------
// Kernel 0: zero the tagged h buffer (fresh tags every launch -> replay-safe)
// ---------------------------------------------------------------------------
__global__ void zero_htag_kernel()
{
    ((unsigned long long*)g_htag)[blockIdx.x * blockDim.x + threadIdx.x] = 0ull;
}

// ---------------------------------------------------------------------------
// Kernel 1: Z = X @ Wx + bias. 128m x 128n tiles, 256 threads, 8x8 microtile.
// ---------------------------------------------------------------------------
__global__ void __launch_bounds__(256)
xproj_kernel(const float* __restrict__ X,
             const float* __restrict__ Wf, const float* __restrict__ bf,
             const float* __restrict__ Wi, const float* __restrict__ bi,
             const float* __restrict__ Wg, const float* __restrict__ bg,
             const float* __restrict__ Wo, const float* __restrict__ bo,
             const float* __restrict__ Wq, const float* __restrict__ bq)
{
    __shared__ float Xs[8][132];   // [k][m]
    __shared__ float Bs[8][132];   // [k][n]

    const int row0 = blockIdx.x * 128;
    const int nt   = blockIdx.y;          // 0..8

    const float* W; const float* bias; int ld, wc0, col0, nvalid;
    if (nt < 8) {
        int gate = nt >> 1;
        W    = (gate == 0) ? Wf : (gate == 1) ? Wi : (gate == 2) ? Wg : Wo;
        bias = (gate == 0) ? bf : (gate == 1) ? bi : (gate == 2) ? bg : bo;
        ld = 256; wc0 = (nt & 1) * 128; col0 = nt * 128; nvalid = 128;
    } else {
        W = Wq; bias = bq; ld = 8; wc0 = 0; col0 = 1024; nvalid = 8;
    }

    const int tid = threadIdx.x;          // 256
    const int tx  = tid & 15;
    const int ty  = tid >> 4;

    float acc[8][8] = {};

    for (int k0 = 0; k0 < 256; k0 += 8) {
        {
            int m = tid >> 1, kq = tid & 1;
            float4 v = *(const float4*)(X + (size_t)(row0 + m) * 256 + k0 + kq * 4);
            Xs[kq * 4 + 0][m] = v.x;
            Xs[kq * 4 + 1][m] = v.y;
            Xs[kq * 4 + 2][m] = v.z;
            Xs[kq * 4 + 3][m] = v.w;
        }
        {
            int k = tid >> 5, n4 = tid & 31;
            float4 w4 = { 0.f, 0.f, 0.f, 0.f };
            if (n4 * 4 < nvalid)
                w4 = *(const float4*)(W + (size_t)(k0 + k) * ld + wc0 + n4 * 4);
            *(float4*)&Bs[k][n4 * 4] = w4;
        }
        __syncthreads();

        #pragma unroll
        for (int kk = 0; kk < 8; kk++) {
            float4 a0 = *(const float4*)&Xs[kk][ty * 4];
            float4 a1 = *(const float4*)&Xs[kk][64 + ty * 4];
            float4 b0 = *(const float4*)&Bs[kk][tx * 4];
            float4 b1 = *(const float4*)&Bs[kk][64 + tx * 4];
            float a[8] = { a0.x, a0.y, a0.z, a0.w, a1.x, a1.y, a1.z, a1.w };
            float b[8] = { b0.x, b0.y, b0.z, b0.w, b1.x, b1.y, b1.z, b1.w };
            #pragma unroll
            for (int i = 0; i < 8; i++)
                #pragma unroll
                for (int j = 0; j < 8; j++)
                    acc[i][j] += a[i] * b[j];
        }
        __syncthreads();
    }

    #pragma unroll
    for (int i = 0; i < 8; i++) {
        int r = row0 + ((i < 4) ? (ty * 4 + i) : (64 + ty * 4 + i - 4));
        #pragma unroll
        for (int j = 0; j < 8; j++) {
            int n = (j < 4) ? (tx * 4 + j) : (64 + tx * 4 + j - 4);
            if (n < nvalid)
                g_Z[(size_t)r * ZLD + col0 + n] = acc[i][j] + bias[wc0 + n];
        }
    }
}

// ---------------------------------------------------------------------------
// packed fp32x2 helpers
// ---------------------------------------------------------------------------
__device__ __forceinline__ unsigned long long pack2(float a, float b) {
    unsigned long long r;
    asm("mov.b64 %0, {%1, %2};" : "=l"(r) : "f"(a), "f"(b));
    return r;
}
__device__ __forceinline__ void unpack2(unsigned long long v, float& a, float& b) {
    asm("mov.b64 {%0, %1}, %2;" : "=f"(a), "=f"(b) : "l"(v));
}
__device__ __forceinline__ void fma2(unsigned long long& d,
                                     unsigned long long a, unsigned long long b) {
    asm("fma.rn.f32x2 %0, %1, %2, %0;" : "+l"(d) : "l"(a), "l"(b));
}
__device__ __forceinline__ float sigmoidf_(float x) {
    return 1.f / (1.f + __expf(-x));
}

// ---------------------------------------------------------------------------
// Kernel 2: persistent recurrence, 128 CTAs (4 b-tiles x 32 u-tiles), 512 thr.
// Transport: tagged 8B packets (tag = t+1, h) in g_htag[t&1]; consumers poll
// the data directly (no barriers, no fences, no atomics). Dot/reduce/owner
// structure identical to the verified round-6 kernel.
// warp = (kch 0..7, rh 0..1); lane = (uu 0..7, kcl 0..3); k chunk = 8.
// ---------------------------------------------------------------------------
__global__ void __launch_bounds__(512, 1)
lstm_persistent(const float* __restrict__ Wf,
                const float* __restrict__ Wi,
                const float* __restrict__ Wg,
                const float* __restrict__ Wo,
                const float* __restrict__ Wq,
                float* __restrict__ stacked,   // [T,B,256]
                float* __restrict__ hx_out,    // [B,256]
                float* __restrict__ cx_out)    // [B,256]
{
    __shared__ float sm_h[16 * 264];        // hx tile, padded rows
    __shared__ float sm_red[16 * 352];      // [warp][uu(44)][c2*20+j*5+g]

    const int tid  = threadIdx.x;           // 512
    const int warp = tid >> 5;              // 0..15
    const int lane = tid & 31;
    const int b0   = blockIdx.x * 16;       // gridDim.x = 4
    const int u0   = blockIdx.y * 8;        // gridDim.y = 32

    const int uu   = lane & 7;
    const int kcl  = lane >> 3;             // 0..3
    const int kch  = warp & 7;              // 0..7
    const int rh   = warp >> 3;             // 0..1
    const int k0   = (kch * 4 + kcl) * 8;   // 8-k chunk base

    // ---- weights: packed k-pairs, 5 gates x 4 pairs, in registers ----
    unsigned long long wv[5][4];
    {
        const float* Wp[4] = { Wf, Wi, Wg, Wo };
        #pragma unroll
        for (int g = 0; g < 4; g++)
            #pragma unroll
            for (int kp = 0; kp < 4; kp++) {
                int k = 256 + k0 + 2 * kp;
                wv[g][kp] = pack2(Wp[g][(size_t)k * 256 + u0 + uu],
                                  Wp[g][(size_t)(k + 1) * 256 + u0 + uu]);
            }
        #pragma unroll
        for (int kp = 0; kp < 4; kp++) {
            int k = 256 + k0 + 2 * kp;
            wv[4][kp] = pack2(Wq[(size_t)k * 8 + uu], Wq[(size_t)(k + 1) * 8 + uu]);
        }
    }

    // ---- poll mapping: thread -> (row, 8 consecutive units) ----
    const int prow = tid >> 5;              // 0..15
    const int pu   = (tid & 31) * 8;        // 0..248

    // ---- owner mapping: tid < 128 -> one (row, unit) output ----
    const int o_row = tid >> 3;
    const int o_uu  = tid & 7;
    const int ob    = b0 + o_row;
    const int oug   = u0 + o_uu;
    const float* o_z = g_Z + (size_t)ob * ZLD;
    float c = 0.f, h = 0.f;

    for (int t = 0; t < T_STEPS; t++) {
        // prefetch Z (independent of recurrence; overlaps the poll)
        float zF = 0.f, zI = 0.f, zG = 0.f, zO = 0.f, zQ = 0.f;
        if (tid < 128) {
            const float* z = o_z + (size_t)t * BATCH * ZLD;
            zF = __ldg(z + oug);
            zI = __ldg(z + 256 + oug);
            zG = __ldg(z + 512 + oug);
            zO = __ldg(z + 768 + oug);
            zQ = __ldg(z + 1024 + o_uu);
        }

        // ---- poll h(t-1) packets (tag == t), or zeros at t == 0 ----
        float4 fa, fb;
        if (t > 0) {
            const unsigned want = (unsigned)t;
            const unsigned long long* src = &g_htag[(t - 1) & 1][b0 + prow][pu];
            unsigned a0,a1,a2,a3, b0v,b1v,b2v,b3v, c0,c1,c2,c3, d0,d1,d2,d3;
            for (;;) {
                asm volatile("ld.volatile.global.v4.u32 {%0,%1,%2,%3}, [%4];"
                             : "=r"(a0),"=r"(a1),"=r"(a2),"=r"(a3) : "l"(src));
                asm volatile("ld.volatile.global.v4.u32 {%0,%1,%2,%3}, [%4];"
                             : "=r"(b0v),"=r"(b1v),"=r"(b2v),"=r"(b3v) : "l"(src + 2));
                asm volatile("ld.volatile.global.v4.u32 {%0,%1,%2,%3}, [%4];"
                             : "=r"(c0),"=r"(c1),"=r"(c2),"=r"(c3) : "l"(src + 4));
                asm volatile("ld.volatile.global.v4.u32 {%0,%1,%2,%3}, [%4];"
                             : "=r"(d0),"=r"(d1),"=r"(d2),"=r"(d3) : "l"(src + 6));
                if (a0 == want && a2 == want && b0v == want && b2v == want &&
                    c0 == want && c2 == want && d0 == want && d2 == want) break;
            }
            fa = make_float4(__uint_as_float(a1), __uint_as_float(a3),
                             __uint_as_float(b1v), __uint_as_float(b3v));
            fb = make_float4(__uint_as_float(c1), __uint_as_float(c3),
                             __uint_as_float(d1), __uint_as_float(d3));
        } else {
            fa = make_float4(0.f, 0.f, 0.f, 0.f);
            fb = fa;
        }

        __syncthreads();   // previous step's sm_h/sm_red reads all done
        *(float4*)(sm_h + prow * 264 + pu)     = fa;
        *(float4*)(sm_h + prow * 264 + pu + 4) = fb;
        __syncthreads();

        // ---- two 4-row passes: packed dots + reduce (verified R6 core) ----
        #pragma unroll
        for (int c2p = 0; c2p < 2; c2p++) {
            unsigned long long acc[4][5];
            #pragma unroll
            for (int j = 0; j < 4; j++)
                #pragma unroll
                for (int g = 0; g < 5; g++) acc[j][g] = 0ull;

            #pragma unroll
            for (int j = 0; j < 4; j++) {
                const float* hrow = sm_h + (rh * 8 + c2p * 4 + j) * 264 + k0;
                float4 hv0 = *(const float4*)(hrow);
                float4 hv1 = *(const float4*)(hrow + 4);
                unsigned long long hk0 = pack2(hv0.x, hv0.y);
                unsigned long long hk1 = pack2(hv0.z, hv0.w);
                unsigned long long hk2 = pack2(hv1.x, hv1.y);
                unsigned long long hk3 = pack2(hv1.z, hv1.w);
                #pragma unroll
                for (int g = 0; g < 5; g++) {
                    fma2(acc[j][g], hk0, wv[g][0]);
                    fma2(acc[j][g], hk1, wv[g][1]);
                    fma2(acc[j][g], hk2, wv[g][2]);
                    fma2(acc[j][g], hk3, wv[g][3]);
                }
            }

            float v[20];
            #pragma unroll
            for (int j = 0; j < 4; j++)
                #pragma unroll
                for (int g = 0; g < 5; g++) {
                    float lo, hi;
                    unpack2(acc[j][g], lo, hi);
                    v[j * 5 + g] = lo + hi;
                }
            #pragma unroll
            for (int m = 0; m < 20; m++) {
                v[m] += __shfl_xor_sync(0xffffffffu, v[m], 8);
                v[m] += __shfl_xor_sync(0xffffffffu, v[m], 16);
            }
            if (kcl == 0) {
                float* dst = sm_red + warp * 352 + uu * 44 + c2p * 20;
                #pragma unroll
                for (int q4 = 0; q4 < 5; q4++)
                    *(float4*)(dst + q4 * 4) = make_float4(v[q4*4], v[q4*4+1],
                                                           v[q4*4+2], v[q4*4+3]);
            }
        }
        __syncthreads();

        // ---- owners finalize + publish tagged packet ----
        if (tid < 128) {
            const int rh_o = o_row >> 3;
            const int rr   = o_row & 7;
            const int c2_o = rr >> 2;
            const int j_o  = rr & 3;
            float aF = zF, aI = zI, aG = zG, aO = zO, aQ = zQ;
            #pragma unroll
            for (int w2 = 0; w2 < 8; w2++) {
                const float* src = sm_red + (rh_o * 8 + w2) * 352 + o_uu * 44
                                 + c2_o * 20 + j_o * 5;
                aF += src[0]; aI += src[1]; aG += src[2]; aO += src[3]; aQ += src[4];
            }

            float s = tanhf(aQ);
            s += __shfl_xor_sync(0xffffffffu, s, 1);
            s += __shfl_xor_sync(0xffffffffu, s, 2);
            s += __shfl_xor_sync(0xffffffffu, s, 4);
            const float qout = sigmoidf_(s);

            const float f = (1.f - QSTR) * sigmoidf_(aF) + QSTR * qout;
            const float i = sigmoidf_(aI);
            const float g = tanhf(aG);
            const float o = sigmoidf_(aO);

            c = f * c + i * g;
            h = o * tanhf(c);

            __stcg(stacked + ((size_t)t * BATCH + ob) * 256 + oug, h);

            const unsigned long long pkt =
                ((unsigned long long)__float_as_uint(h) << 32)
                | (unsigned long long)(unsigned)(t + 1);
            __stcg(&g_htag[t & 1][ob][oug], pkt);
        }
        // no barrier: next iteration's top syncthreads protects smem reuse
    }

    if (tid < 128) {
        hx_out[ob * 256 + oug] = h;
        cx_out[ob * 256 + oug] = c;
    }
}

// ---------------------------------------------------------------------------
extern "C" void kernel_launch(void* const* d_in, const int* in_sizes, int n_in,
                              void* d_out, int out_size)
{
    const float* X  = (const float*)d_in[0];
    const float* Wf = (const float*)d_in[1];
    const float* bf = (const float*)d_in[2];
    const float* Wi = (const float*)d_in[3];
    const float* bi = (const float*)d_in[4];
    const float* Wg = (const float*)d_in[5];
    const float* bg = (const float*)d_in[6];
    const float* Wo = (const float*)d_in[7];
    const float* bo = (const float*)d_in[8];
    const float* Wq = (const float*)d_in[9];
    const float* bq = (const float*)d_in[10];

    float* out     = (float*)d_out;
    float* stacked = out;                                  // [T,B,256]
    float* hx_out  = out + (size_t)T_STEPS * BATCH * 256;  // [B,256]
    float* cx_out  = hx_out + BATCH * 256;                 // [B,256]

    // 0) reset tagged h buffer (2*64*256 = 32768 packets)
    zero_htag_kernel<<<64, 512>>>();

    // 1) precompute input projections
    dim3 g1(T_STEPS * BATCH / 128, 9);
    xproj_kernel<<<g1, 256>>>(X, Wf, bf, Wi, bi, Wg, bg, Wo, bo, Wq, bq);

    // 2) persistent recurrence (barrier-free tagged-packet dataflow)
    dim3 g2(4, 32);
    lstm_persistent<<<g2, 512>>>(Wf, Wi, Wg, Wo, Wq, stacked, hx_out, cx_out);
}

// round 11
// speedup vs baseline: 1.2151x; 1.1468x over previous
#include <cuda_runtime.h>
#include <cstddef>
#include <cstdint>

#define T_STEPS 2048
#define BATCH   64
#define ZLD     1032         // 4*256 + 8
#define QSTR    0.5f

// ---------------- scratch (static device globals; no allocation) ------------
__device__ float g_Z[(size_t)T_STEPS * BATCH * ZLD];   // x-projection + bias
__device__ unsigned g_flag[128 * 32];                  // per-CTA flag, 128B apart

// ---------------------------------------------------------------------------
// Kernel 0: zero the flags (monotonic counters; fresh each launch)
// ---------------------------------------------------------------------------
__global__ void zero_flags_kernel()
{
    g_flag[blockIdx.x * blockDim.x + threadIdx.x] = 0u;
}

// ---------------------------------------------------------------------------
// Kernel 1: Z = X @ Wx + bias. 128m x 128n tiles, 256 threads, 8x8 microtile
// computed as 8x4 packed fp32x2 FFMA2 (half the FMA issue of scalar).
// ---------------------------------------------------------------------------
__device__ __forceinline__ unsigned long long pack2(float a, float b) {
    unsigned long long r;
    asm("mov.b64 %0, {%1, %2};" : "=l"(r) : "f"(a), "f"(b));
    return r;
}
__device__ __forceinline__ void unpack2(unsigned long long v, float& a, float& b) {
    asm("mov.b64 {%0, %1}, %2;" : "=f"(a), "=f"(b) : "l"(v));
}
__device__ __forceinline__ void fma2(unsigned long long& d,
                                     unsigned long long a, unsigned long long b) {
    asm("fma.rn.f32x2 %0, %1, %2, %0;" : "+l"(d) : "l"(a), "l"(b));
}

__global__ void __launch_bounds__(256)
xproj_kernel(const float* __restrict__ X,
             const float* __restrict__ Wf, const float* __restrict__ bf,
             const float* __restrict__ Wi, const float* __restrict__ bi,
             const float* __restrict__ Wg, const float* __restrict__ bg,
             const float* __restrict__ Wo, const float* __restrict__ bo,
             const float* __restrict__ Wq, const float* __restrict__ bq)
{
    __shared__ float Xs[8][132];   // [k][m]
    __shared__ float Bs[8][132];   // [k][n]

    const int row0 = blockIdx.x * 128;
    const int nt   = blockIdx.y;          // 0..8

    const float* W; const float* bias; int ld, wc0, col0, nvalid;
    if (nt < 8) {
        int gate = nt >> 1;
        W    = (gate == 0) ? Wf : (gate == 1) ? Wi : (gate == 2) ? Wg : Wo;
        bias = (gate == 0) ? bf : (gate == 1) ? bi : (gate == 2) ? bg : bo;
        ld = 256; wc0 = (nt & 1) * 128; col0 = nt * 128; nvalid = 128;
    } else {
        W = Wq; bias = bq; ld = 8; wc0 = 0; col0 = 1024; nvalid = 8;
    }

    const int tid = threadIdx.x;          // 256
    const int tx  = tid & 15;
    const int ty  = tid >> 4;

    unsigned long long acc2[8][4];
    #pragma unroll
    for (int i = 0; i < 8; i++)
        #pragma unroll
        for (int j = 0; j < 4; j++) acc2[i][j] = 0ull;

    for (int k0 = 0; k0 < 256; k0 += 8) {
        {
            int m = tid >> 1, kq = tid & 1;
            float4 v = *(const float4*)(X + (size_t)(row0 + m) * 256 + k0 + kq * 4);
            Xs[kq * 4 + 0][m] = v.x;
            Xs[kq * 4 + 1][m] = v.y;
            Xs[kq * 4 + 2][m] = v.z;
            Xs[kq * 4 + 3][m] = v.w;
        }
        {
            int k = tid >> 5, n4 = tid & 31;
            float4 w4 = { 0.f, 0.f, 0.f, 0.f };
            if (n4 * 4 < nvalid)
                w4 = *(const float4*)(W + (size_t)(k0 + k) * ld + wc0 + n4 * 4);
            *(float4*)&Bs[k][n4 * 4] = w4;
        }
        __syncthreads();

        #pragma unroll
        for (int kk = 0; kk < 8; kk++) {
            float4 a0 = *(const float4*)&Xs[kk][ty * 4];
            float4 a1 = *(const float4*)&Xs[kk][64 + ty * 4];
            float4 b0 = *(const float4*)&Bs[kk][tx * 4];
            float4 b1 = *(const float4*)&Bs[kk][64 + tx * 4];
            unsigned long long bp[4] = {
                pack2(b0.x, b0.y), pack2(b0.z, b0.w),
                pack2(b1.x, b1.y), pack2(b1.z, b1.w)
            };
            float a[8] = { a0.x, a0.y, a0.z, a0.w, a1.x, a1.y, a1.z, a1.w };
            #pragma unroll
            for (int i = 0; i < 8; i++) {
                unsigned long long ap = pack2(a[i], a[i]);
                fma2(acc2[i][0], ap, bp[0]);
                fma2(acc2[i][1], ap, bp[1]);
                fma2(acc2[i][2], ap, bp[2]);
                fma2(acc2[i][3], ap, bp[3]);
            }
        }
        __syncthreads();
    }

    #pragma unroll
    for (int i = 0; i < 8; i++) {
        int r = row0 + ((i < 4) ? (ty * 4 + i) : (64 + ty * 4 + i - 4));
        #pragma unroll
        for (int j = 0; j < 4; j++) {
            int nb = (j < 2) ? (tx * 4 + j * 2) : (64 + tx * 4 + (j - 2) * 2);
            float lo, hi;
            unpack2(acc2[i][j], lo, hi);
            if (nb < nvalid)
                g_Z[(size_t)r * ZLD + col0 + nb] = lo + bias[wc0 + nb];
            if (nb + 1 < nvalid)
                g_Z[(size_t)r * ZLD + col0 + nb + 1] = hi + bias[wc0 + nb + 1];
        }
    }
}

__device__ __forceinline__ float sigmoidf_(float x) {
    return 1.f / (1.f + __expf(-x));
}

// ---------------------------------------------------------------------------
// Kernel 2: persistent recurrence, 128 CTAs (4 b-tiles x 32 u-tiles), 512 thr.
// Verified R6 compute core. Transport: owners st.cg h into stacked[t], then
// red.release.gpu.add(1) to this CTA's flag (orders each owner's own store).
// Consumers: 32 threads ld.acquire-poll the group's 32 flags for >= 128*t,
// then stage stacked[t-1] via ldcg. No fences, no nanosleep, no barriers.
// ---------------------------------------------------------------------------
__global__ void __launch_bounds__(512, 1)
lstm_persistent(const float* __restrict__ Wf,
                const float* __restrict__ Wi,
                const float* __restrict__ Wg,
                const float* __restrict__ Wo,
                const float* __restrict__ Wq,
                float* __restrict__ stacked,   // [T,B,256]
                float* __restrict__ hx_out,    // [B,256]
                float* __restrict__ cx_out)    // [B,256]
{
    __shared__ float sm_h[16 * 264];        // hx tile, padded rows
    __shared__ float sm_red[16 * 352];      // [warp][uu(44)][c2*20+j*5+g]

    const int tid  = threadIdx.x;           // 512
    const int warp = tid >> 5;              // 0..15
    const int lane = tid & 31;
    const int b0   = blockIdx.x * 16;       // gridDim.x = 4
    const int u0   = blockIdx.y * 8;        // gridDim.y = 32

    const int uu   = lane & 7;
    const int kcl  = lane >> 3;             // 0..3
    const int kch  = warp & 7;              // 0..7
    const int rh   = warp >> 3;             // 0..1
    const int k0   = (kch * 4 + kcl) * 8;   // 8-k chunk base

    unsigned* myflag = &g_flag[(blockIdx.x * 32 + blockIdx.y) * 32];

    // ---- weights: packed k-pairs, 5 gates x 4 pairs, in registers ----
    unsigned long long wv[5][4];
    {
        const float* Wp[4] = { Wf, Wi, Wg, Wo };
        #pragma unroll
        for (int g = 0; g < 4; g++)
            #pragma unroll
            for (int kp = 0; kp < 4; kp++) {
                int k = 256 + k0 + 2 * kp;
                wv[g][kp] = pack2(Wp[g][(size_t)k * 256 + u0 + uu],
                                  Wp[g][(size_t)(k + 1) * 256 + u0 + uu]);
            }
        #pragma unroll
        for (int kp = 0; kp < 4; kp++) {
            int k = 256 + k0 + 2 * kp;
            wv[4][kp] = pack2(Wq[(size_t)k * 8 + uu], Wq[(size_t)(k + 1) * 8 + uu]);
        }
    }

    // ---- owner mapping: tid < 128 -> one (row, unit) output ----
    const int o_row = tid >> 3;
    const int o_uu  = tid & 7;
    const int ob    = b0 + o_row;
    const int oug   = u0 + o_uu;
    const float* o_z = g_Z + (size_t)ob * ZLD;
    float c = 0.f, h = 0.f;

    for (int t = 0; t < T_STEPS; t++) {
        // prefetch Z (independent of recurrence; overlaps the poll)
        float zF = 0.f, zI = 0.f, zG = 0.f, zO = 0.f, zQ = 0.f;
        if (tid < 128) {
            const float* z = o_z + (size_t)t * BATCH * ZLD;
            zF = __ldg(z + oug);
            zI = __ldg(z + 256 + oug);
            zG = __ldg(z + 512 + oug);
            zO = __ldg(z + 768 + oug);
            zQ = __ldg(z + 1024 + o_uu);
        }

        // ---- wait: all 32 CTAs of this b-group published h(t-1) ----
        if (t > 0) {
            if (tid < 32) {
                const unsigned want = (unsigned)t * 128u;
                const unsigned* fp = &g_flag[(blockIdx.x * 32 + tid) * 32];
                unsigned v;
                do {
                    asm volatile("ld.acquire.gpu.global.u32 %0, [%1];"
                                 : "=r"(v) : "l"(fp));
                } while (v < want);
            }
            __syncthreads();
        }

        // ---- stage hx tile (stacked[t-1], zeros at t==0) ----
        const float4* hsrc = (const float4*)(stacked + ((size_t)(t - 1) * BATCH + b0) * 256);
        #pragma unroll
        for (int i = 0; i < 2; i++) {
            int idx = tid + i * 512;            // 0..1023
            int row = idx >> 6, k4 = idx & 63;
            float4 v;
            if (t == 0) { v.x = v.y = v.z = v.w = 0.f; }
            else        { v = __ldcg(hsrc + (size_t)row * 64 + k4); }
            *(float4*)(sm_h + row * 264 + k4 * 4) = v;
        }
        __syncthreads();

        // ---- two 4-row passes: packed dots + reduce (verified R6 core) ----
        #pragma unroll
        for (int c2p = 0; c2p < 2; c2p++) {
            unsigned long long acc[4][5];
            #pragma unroll
            for (int j = 0; j < 4; j++)
                #pragma unroll
                for (int g = 0; g < 5; g++) acc[j][g] = 0ull;

            #pragma unroll
            for (int j = 0; j < 4; j++) {
                const float* hrow = sm_h + (rh * 8 + c2p * 4 + j) * 264 + k0;
                float4 hv0 = *(const float4*)(hrow);
                float4 hv1 = *(const float4*)(hrow + 4);
                unsigned long long hk0 = pack2(hv0.x, hv0.y);
                unsigned long long hk1 = pack2(hv0.z, hv0.w);
                unsigned long long hk2 = pack2(hv1.x, hv1.y);
                unsigned long long hk3 = pack2(hv1.z, hv1.w);
                #pragma unroll
                for (int g = 0; g < 5; g++) {
                    fma2(acc[j][g], hk0, wv[g][0]);
                    fma2(acc[j][g], hk1, wv[g][1]);
                    fma2(acc[j][g], hk2, wv[g][2]);
                    fma2(acc[j][g], hk3, wv[g][3]);
                }
            }

            float v[20];
            #pragma unroll
            for (int j = 0; j < 4; j++)
                #pragma unroll
                for (int g = 0; g < 5; g++) {
                    float lo, hi;
                    unpack2(acc[j][g], lo, hi);
                    v[j * 5 + g] = lo + hi;
                }
            #pragma unroll
            for (int m = 0; m < 20; m++) {
                v[m] += __shfl_xor_sync(0xffffffffu, v[m], 8);
                v[m] += __shfl_xor_sync(0xffffffffu, v[m], 16);
            }
            if (kcl == 0) {
                float* dst = sm_red + warp * 352 + uu * 44 + c2p * 20;
                #pragma unroll
                for (int q4 = 0; q4 < 5; q4++)
                    *(float4*)(dst + q4 * 4) = make_float4(v[q4*4], v[q4*4+1],
                                                           v[q4*4+2], v[q4*4+3]);
            }
        }
        __syncthreads();

        // ---- owners finalize + publish (store then release-add) ----
        if (tid < 128) {
            const int rh_o = o_row >> 3;
            const int rr   = o_row & 7;
            const int c2_o = rr >> 2;
            const int j_o  = rr & 3;
            float aF = zF, aI = zI, aG = zG, aO = zO, aQ = zQ;
            #pragma unroll
            for (int w2 = 0; w2 < 8; w2++) {
                const float* src = sm_red + (rh_o * 8 + w2) * 352 + o_uu * 44
                                 + c2_o * 20 + j_o * 5;
                aF += src[0]; aI += src[1]; aG += src[2]; aO += src[3]; aQ += src[4];
            }

            float s = tanhf(aQ);
            s += __shfl_xor_sync(0xffffffffu, s, 1);
            s += __shfl_xor_sync(0xffffffffu, s, 2);
            s += __shfl_xor_sync(0xffffffffu, s, 4);
            const float qout = sigmoidf_(s);

            const float f = (1.f - QSTR) * sigmoidf_(aF) + QSTR * qout;
            const float i = sigmoidf_(aI);
            const float g = tanhf(aG);
            const float o = sigmoidf_(aO);

            c = f * c + i * g;
            h = o * tanhf(c);

            __stcg(stacked + ((size_t)t * BATCH + ob) * 256 + oug, h);
            // release orders THIS thread's h store before the flag increment
            asm volatile("red.release.gpu.global.add.u32 [%0], %1;"
                         :: "l"(myflag), "r"(1u) : "memory");
        }
        // no trailing barrier: next iteration's syncs protect smem reuse
    }

    if (tid < 128) {
        hx_out[ob * 256 + oug] = h;
        cx_out[ob * 256 + oug] = c;
    }
}

// ---------------------------------------------------------------------------
extern "C" void kernel_launch(void* const* d_in, const int* in_sizes, int n_in,
                              void* d_out, int out_size)
{
    const float* X  = (const float*)d_in[0];
    const float* Wf = (const float*)d_in[1];
    const float* bf = (const float*)d_in[2];
    const float* Wi = (const float*)d_in[3];
    const float* bi = (const float*)d_in[4];
    const float* Wg = (const float*)d_in[5];
    const float* bg = (const float*)d_in[6];
    const float* Wo = (const float*)d_in[7];
    const float* bo = (const float*)d_in[8];
    const float* Wq = (const float*)d_in[9];
    const float* bq = (const float*)d_in[10];

    float* out     = (float*)d_out;
    float* stacked = out;                                  // [T,B,256]
    float* hx_out  = out + (size_t)T_STEPS * BATCH * 256;  // [B,256]
    float* cx_out  = hx_out + BATCH * 256;                 // [B,256]

    // 0) reset flags (4096 u32)
    zero_flags_kernel<<<8, 512>>>();

    // 1) precompute input projections (packed FFMA2 GEMM)
    dim3 g1(T_STEPS * BATCH / 128, 9);
    xproj_kernel<<<g1, 256>>>(X, Wf, bf, Wi, bi, Wg, bg, Wo, bo, Wq, bq);

    // 2) persistent recurrence (release-counter dataflow)
    dim3 g2(4, 32);
    lstm_persistent<<<g2, 512>>>(Wf, Wi, Wg, Wo, Wq, stacked, hx_out, cx_out);
}

// round 12
// speedup vs baseline: 1.2363x; 1.0175x over previous
#include <cuda_runtime.h>
#include <cstddef>
#include <cstdint>

#define T_STEPS 2048
#define BATCH   64
#define ZLD     1032         // 4*256 + 8
#define QSTR    0.5f

// ---------------- scratch (static device globals; no allocation) ------------
__device__ float g_Z[(size_t)T_STEPS * BATCH * ZLD];   // x-projection + bias
__device__ unsigned g_flag[256 * 32];                  // per-CTA flag, 128B apart

// ---------------------------------------------------------------------------
// Kernel 0: zero the flags (monotonic counters; fresh each launch)
// ---------------------------------------------------------------------------
__global__ void zero_flags_kernel()
{
    g_flag[blockIdx.x * blockDim.x + threadIdx.x] = 0u;
}

// ---------------------------------------------------------------------------
// packed fp32x2 helpers
// ---------------------------------------------------------------------------
__device__ __forceinline__ unsigned long long pack2(float a, float b) {
    unsigned long long r;
    asm("mov.b64 %0, {%1, %2};" : "=l"(r) : "f"(a), "f"(b));
    return r;
}
__device__ __forceinline__ void unpack2(unsigned long long v, float& a, float& b) {
    asm("mov.b64 {%0, %1}, %2;" : "=f"(a), "=f"(b) : "l"(v));
}
__device__ __forceinline__ void fma2(unsigned long long& d,
                                     unsigned long long a, unsigned long long b) {
    asm("fma.rn.f32x2 %0, %1, %2, %0;" : "+l"(d) : "l"(a), "l"(b));
}

// ---------------------------------------------------------------------------
// Kernel 1: Z = X @ Wx + bias. 128m x 128n tiles, 256 threads, packed FFMA2.
// ---------------------------------------------------------------------------
__global__ void __launch_bounds__(256)
xproj_kernel(const float* __restrict__ X,
             const float* __restrict__ Wf, const float* __restrict__ bf,
             const float* __restrict__ Wi, const float* __restrict__ bi,
             const float* __restrict__ Wg, const float* __restrict__ bg,
             const float* __restrict__ Wo, const float* __restrict__ bo,
             const float* __restrict__ Wq, const float* __restrict__ bq)
{
    __shared__ float Xs[8][132];   // [k][m]
    __shared__ float Bs[8][132];   // [k][n]

    const int row0 = blockIdx.x * 128;
    const int nt   = blockIdx.y;          // 0..8

    const float* W; const float* bias; int ld, wc0, col0, nvalid;
    if (nt < 8) {
        int gate = nt >> 1;
        W    = (gate == 0) ? Wf : (gate == 1) ? Wi : (gate == 2) ? Wg : Wo;
        bias = (gate == 0) ? bf : (gate == 1) ? bi : (gate == 2) ? bg : bo;
        ld = 256; wc0 = (nt & 1) * 128; col0 = nt * 128; nvalid = 128;
    } else {
        W = Wq; bias = bq; ld = 8; wc0 = 0; col0 = 1024; nvalid = 8;
    }

    const int tid = threadIdx.x;          // 256
    const int tx  = tid & 15;
    const int ty  = tid >> 4;

    unsigned long long acc2[8][4];
    #pragma unroll
    for (int i = 0; i < 8; i++)
        #pragma unroll
        for (int j = 0; j < 4; j++) acc2[i][j] = 0ull;

    for (int k0 = 0; k0 < 256; k0 += 8) {
        {
            int m = tid >> 1, kq = tid & 1;
            float4 v = *(const float4*)(X + (size_t)(row0 + m) * 256 + k0 + kq * 4);
            Xs[kq * 4 + 0][m] = v.x;
            Xs[kq * 4 + 1][m] = v.y;
            Xs[kq * 4 + 2][m] = v.z;
            Xs[kq * 4 + 3][m] = v.w;
        }
        {
            int k = tid >> 5, n4 = tid & 31;
            float4 w4 = { 0.f, 0.f, 0.f, 0.f };
            if (n4 * 4 < nvalid)
                w4 = *(const float4*)(W + (size_t)(k0 + k) * ld + wc0 + n4 * 4);
            *(float4*)&Bs[k][n4 * 4] = w4;
        }
        __syncthreads();

        #pragma unroll
        for (int kk = 0; kk < 8; kk++) {
            float4 a0 = *(const float4*)&Xs[kk][ty * 4];
            float4 a1 = *(const float4*)&Xs[kk][64 + ty * 4];
            float4 b0 = *(const float4*)&Bs[kk][tx * 4];
            float4 b1 = *(const float4*)&Bs[kk][64 + tx * 4];
            unsigned long long bp[4] = {
                pack2(b0.x, b0.y), pack2(b0.z, b0.w),
                pack2(b1.x, b1.y), pack2(b1.z, b1.w)
            };
            float a[8] = { a0.x, a0.y, a0.z, a0.w, a1.x, a1.y, a1.z, a1.w };
            #pragma unroll
            for (int i = 0; i < 8; i++) {
                unsigned long long ap = pack2(a[i], a[i]);
                fma2(acc2[i][0], ap, bp[0]);
                fma2(acc2[i][1], ap, bp[1]);
                fma2(acc2[i][2], ap, bp[2]);
                fma2(acc2[i][3], ap, bp[3]);
            }
        }
        __syncthreads();
    }

    #pragma unroll
    for (int i = 0; i < 8; i++) {
        int r = row0 + ((i < 4) ? (ty * 4 + i) : (64 + ty * 4 + i - 4));
        #pragma unroll
        for (int j = 0; j < 4; j++) {
            int nb = (j < 2) ? (tx * 4 + j * 2) : (64 + tx * 4 + (j - 2) * 2);
            float lo, hi;
            unpack2(acc2[i][j], lo, hi);
            if (nb < nvalid)
                g_Z[(size_t)r * ZLD + col0 + nb] = lo + bias[wc0 + nb];
            if (nb + 1 < nvalid)
                g_Z[(size_t)r * ZLD + col0 + nb + 1] = hi + bias[wc0 + nb + 1];
        }
    }
}

__device__ __forceinline__ float sigmoidf_(float x) {
    return 1.f / (1.f + __expf(-x));
}

// ---------------------------------------------------------------------------
// Kernel 2: persistent recurrence, 256 CTAs (8 b-groups x 32 u-tiles),
// 256 threads, 2 CTAs/SM co-resident (stall interleaving).
// CTA owns 8 batch rows x 8 units. warp = kch 0..7; lane = (uu 0..7, kcl 0..3);
// kc = kch*4+kcl -> 32 chunks of 8 k. Weights (5 gates x 4 packed k-pairs) in
// registers. Per step: stage hx, row-at-a-time packed dots + in-warp kcl
// reduce, sm_red cross-warp (kch), 64 owners finalize + publish via
// st.cg + red.release to this CTA's flag; consumers acquire-poll 32 flags.
// ---------------------------------------------------------------------------
__global__ void __launch_bounds__(256, 2)
lstm_persistent(const float* __restrict__ Wf,
                const float* __restrict__ Wi,
                const float* __restrict__ Wg,
                const float* __restrict__ Wo,
                const float* __restrict__ Wq,
                float* __restrict__ stacked,   // [T,B,256]
                float* __restrict__ hx_out,    // [B,256]
                float* __restrict__ cx_out)    // [B,256]
{
    __shared__ float sm_h[8 * 264];         // hx tile: 8 rows, padded
    __shared__ float sm_red[8 * 8 * 41];    // [warp(kch)][uu][row*5] (+pad)

    const int tid  = threadIdx.x;           // 256
    const int warp = tid >> 5;              // 0..7  = kch
    const int lane = tid & 31;
    const int b0   = blockIdx.x * 8;        // gridDim.x = 8
    const int u0   = blockIdx.y * 8;        // gridDim.y = 32

    const int uu   = lane & 7;
    const int kcl  = lane >> 3;             // 0..3
    const int k0   = warp * 32 + kcl * 8;   // 8-k chunk base

    unsigned* myflag = &g_flag[(blockIdx.x * 32 + blockIdx.y) * 32];

    // ---- weights: packed k-pairs, 5 gates x 4 pairs, in registers ----
    unsigned long long wv[5][4];
    {
        const float* Wp[4] = { Wf, Wi, Wg, Wo };
        #pragma unroll
        for (int g = 0; g < 4; g++)
            #pragma unroll
            for (int kp = 0; kp < 4; kp++) {
                int k = 256 + k0 + 2 * kp;
                wv[g][kp] = pack2(Wp[g][(size_t)k * 256 + u0 + uu],
                                  Wp[g][(size_t)(k + 1) * 256 + u0 + uu]);
            }
        #pragma unroll
        for (int kp = 0; kp < 4; kp++) {
            int k = 256 + k0 + 2 * kp;
            wv[4][kp] = pack2(Wq[(size_t)k * 8 + uu], Wq[(size_t)(k + 1) * 8 + uu]);
        }
    }

    // ---- owner mapping: tid < 64 -> one (row, unit) output ----
    const int o_row = tid >> 3;             // 0..7 (valid when tid<64)
    const int o_uu  = tid & 7;
    const int ob    = b0 + o_row;
    const int oug   = u0 + o_uu;
    const float* o_z = g_Z + (size_t)ob * ZLD;
    float c = 0.f, h = 0.f;

    for (int t = 0; t < T_STEPS; t++) {
        // prefetch Z (independent of recurrence; overlaps the poll)
        float zF = 0.f, zI = 0.f, zG = 0.f, zO = 0.f, zQ = 0.f;
        if (tid < 64) {
            const float* z = o_z + (size_t)t * BATCH * ZLD;
            zF = __ldg(z + oug);
            zI = __ldg(z + 256 + oug);
            zG = __ldg(z + 512 + oug);
            zO = __ldg(z + 768 + oug);
            zQ = __ldg(z + 1024 + o_uu);
        }

        // ---- wait: all 32 CTAs of this b-group published h(t-1) ----
        if (t > 0) {
            if (tid < 32) {
                const unsigned want = (unsigned)t * 64u;
                const unsigned* fp = &g_flag[(blockIdx.x * 32 + tid) * 32];
                unsigned v;
                do {
                    asm volatile("ld.acquire.gpu.global.u32 %0, [%1];"
                                 : "=r"(v) : "l"(fp));
                } while (v < want);
            }
            __syncthreads();
        }

        // ---- stage hx tile (stacked[t-1], zeros at t==0): 8x256 floats ----
        const float4* hsrc = (const float4*)(stacked + ((size_t)(t - 1) * BATCH + b0) * 256);
        #pragma unroll
        for (int i = 0; i < 2; i++) {
            int idx = tid + i * 256;            // 0..511
            int row = idx >> 6, k4 = idx & 63;
            float4 v;
            if (t == 0) { v.x = v.y = v.z = v.w = 0.f; }
            else        { v = __ldcg(hsrc + (size_t)row * 64 + k4); }
            *(float4*)(sm_h + row * 264 + k4 * 4) = v;
        }
        __syncthreads();

        // ---- row-at-a-time packed dots + in-warp kcl reduce ----
        #pragma unroll
        for (int j = 0; j < 8; j++) {
            const float* hrow = sm_h + j * 264 + k0;
            float4 hv0 = *(const float4*)(hrow);
            float4 hv1 = *(const float4*)(hrow + 4);
            unsigned long long hk0 = pack2(hv0.x, hv0.y);
            unsigned long long hk1 = pack2(hv0.z, hv0.w);
            unsigned long long hk2 = pack2(hv1.x, hv1.y);
            unsigned long long hk3 = pack2(hv1.z, hv1.w);

            unsigned long long acc[5] = { 0ull, 0ull, 0ull, 0ull, 0ull };
            #pragma unroll
            for (int g = 0; g < 5; g++) {
                fma2(acc[g], hk0, wv[g][0]);
                fma2(acc[g], hk1, wv[g][1]);
                fma2(acc[g], hk2, wv[g][2]);
                fma2(acc[g], hk3, wv[g][3]);
            }

            float v[5];
            #pragma unroll
            for (int g = 0; g < 5; g++) {
                float lo, hi;
                unpack2(acc[g], lo, hi);
                v[g] = lo + hi;
            }
            #pragma unroll
            for (int g = 0; g < 5; g++) {
                v[g] += __shfl_xor_sync(0xffffffffu, v[g], 8);
                v[g] += __shfl_xor_sync(0xffffffffu, v[g], 16);
            }
            if (kcl == 0) {
                float* dst = sm_red + (warp * 8 + uu) * 41 + j * 5;
                #pragma unroll
                for (int g = 0; g < 5; g++) dst[g] = v[g];
            }
        }
        __syncthreads();

        // ---- owners finalize + publish (store then release-add) ----
        if (tid < 64) {
            float aF = zF, aI = zI, aG = zG, aO = zO, aQ = zQ;
            #pragma unroll
            for (int w = 0; w < 8; w++) {   // kch partials
                const float* src = sm_red + (w * 8 + o_uu) * 41 + o_row * 5;
                aF += src[0]; aI += src[1]; aG += src[2]; aO += src[3]; aQ += src[4];
            }

            // q blend: lanes of one row are 8 consecutive threads (uu bits 0..2)
            float s = tanhf(aQ);
            s += __shfl_xor_sync(0xffffffffu, s, 1);
            s += __shfl_xor_sync(0xffffffffu, s, 2);
            s += __shfl_xor_sync(0xffffffffu, s, 4);
            const float qout = sigmoidf_(s);

            const float f = (1.f - QSTR) * sigmoidf_(aF) + QSTR * qout;
            const float i = sigmoidf_(aI);
            const float g = tanhf(aG);
            const float o = sigmoidf_(aO);

            c = f * c + i * g;
            h = o * tanhf(c);

            __stcg(stacked + ((size_t)t * BATCH + ob) * 256 + oug, h);
            // release orders THIS thread's h store before the flag increment
            asm volatile("red.release.gpu.global.add.u32 [%0], %1;"
                         :: "l"(myflag), "r"(1u) : "memory");
        }
        // no trailing barrier: next iteration's syncs protect smem reuse
    }

    if (tid < 64) {
        hx_out[ob * 256 + oug] = h;
        cx_out[ob * 256 + oug] = c;
    }
}

// ---------------------------------------------------------------------------
extern "C" void kernel_launch(void* const* d_in, const int* in_sizes, int n_in,
                              void* d_out, int out_size)
{
    const float* X  = (const float*)d_in[0];
    const float* Wf = (const float*)d_in[1];
    const float* bf = (const float*)d_in[2];
    const float* Wi = (const float*)d_in[3];
    const float* bi = (const float*)d_in[4];
    const float* Wg = (const float*)d_in[5];
    const float* bg = (const float*)d_in[6];
    const float* Wo = (const float*)d_in[7];
    const float* bo = (const float*)d_in[8];
    const float* Wq = (const float*)d_in[9];
    const float* bq = (const float*)d_in[10];

    float* out     = (float*)d_out;
    float* stacked = out;                                  // [T,B,256]
    float* hx_out  = out + (size_t)T_STEPS * BATCH * 256;  // [B,256]
    float* cx_out  = hx_out + BATCH * 256;                 // [B,256]

    // 0) reset flags (8192 u32)
    zero_flags_kernel<<<16, 512>>>();

    // 1) precompute input projections (packed FFMA2 GEMM)
    dim3 g1(T_STEPS * BATCH / 128, 9);
    xproj_kernel<<<g1, 256>>>(X, Wf, bf, Wi, bi, Wg, bg, Wo, bo, Wq, bq);

    // 2) persistent recurrence: 256 CTAs, 2 co-resident per SM
    dim3 g2(8, 32);
    lstm_persistent<<<g2, 256>>>(Wf, Wi, Wg, Wo, Wq, stacked, hx_out, cx_out);
}

// round 14
// speedup vs baseline: 1.2589x; 1.0183x over previous
#include <cuda_runtime.h>
#include <cstddef>
#include <cstdint>

#define T_STEPS 2048
#define BATCH   64
#define D_IN    256
#define D_H     256
#define NQ      8
#define ZLD     1032         // 4*256 + 8
#define QSTR    0.5f
#define GRP_CTAS 32          // CTAs per barrier group (one b-tile)

// ---------------- scratch (static device globals; no allocation) ------------
__device__ float g_Z[(size_t)T_STEPS * BATCH * ZLD];   // x-projection + bias
__device__ unsigned long long g_ctr[4 * 16];           // per-group monotonic ctr

// ---------------------------------------------------------------------------
// packed fp32x2 helpers
// ---------------------------------------------------------------------------
__device__ __forceinline__ unsigned long long pack2(float a, float b) {
    unsigned long long r;
    asm("mov.b64 %0, {%1, %2};" : "=l"(r) : "f"(a), "f"(b));
    return r;
}
__device__ __forceinline__ void unpack2(unsigned long long v, float& a, float& b) {
    asm("mov.b64 {%0, %1}, %2;" : "=f"(a), "=f"(b) : "l"(v));
}
__device__ __forceinline__ void fma2(unsigned long long& d,
                                     unsigned long long a, unsigned long long b) {
    asm("fma.rn.f32x2 %0, %1, %2, %0;" : "+l"(d) : "l"(a), "l"(b));
}

// ---------------------------------------------------------------------------
// Kernel 1: Z = X @ Wx + bias. 128m x 128n tiles, 256 threads, packed FFMA2
// (verified in rounds 11/12).
// ---------------------------------------------------------------------------
__global__ void __launch_bounds__(256)
xproj_kernel(const float* __restrict__ X,
             const float* __restrict__ Wf, const float* __restrict__ bf,
             const float* __restrict__ Wi, const float* __restrict__ bi,
             const float* __restrict__ Wg, const float* __restrict__ bg,
             const float* __restrict__ Wo, const float* __restrict__ bo,
             const float* __restrict__ Wq, const float* __restrict__ bq)
{
    __shared__ float Xs[8][132];   // [k][m]
    __shared__ float Bs[8][132];   // [k][n]

    const int row0 = blockIdx.x * 128;
    const int nt   = blockIdx.y;          // 0..8

    const float* W; const float* bias; int ld, wc0, col0, nvalid;
    if (nt < 8) {
        int gate = nt >> 1;
        W    = (gate == 0) ? Wf : (gate == 1) ? Wi : (gate == 2) ? Wg : Wo;
        bias = (gate == 0) ? bf : (gate == 1) ? bi : (gate == 2) ? bg : bo;
        ld = 256; wc0 = (nt & 1) * 128; col0 = nt * 128; nvalid = 128;
    } else {
        W = Wq; bias = bq; ld = 8; wc0 = 0; col0 = 1024; nvalid = 8;
    }

    const int tid = threadIdx.x;          // 256
    const int tx  = tid & 15;
    const int ty  = tid >> 4;

    unsigned long long acc2[8][4];
    #pragma unroll
    for (int i = 0; i < 8; i++)
        #pragma unroll
        for (int j = 0; j < 4; j++) acc2[i][j] = 0ull;

    for (int k0 = 0; k0 < 256; k0 += 8) {
        {
            int m = tid >> 1, kq = tid & 1;
            float4 v = *(const float4*)(X + (size_t)(row0 + m) * 256 + k0 + kq * 4);
            Xs[kq * 4 + 0][m] = v.x;
            Xs[kq * 4 + 1][m] = v.y;
            Xs[kq * 4 + 2][m] = v.z;
            Xs[kq * 4 + 3][m] = v.w;
        }
        {
            int k = tid >> 5, n4 = tid & 31;
            float4 w4 = { 0.f, 0.f, 0.f, 0.f };
            if (n4 * 4 < nvalid)
                w4 = *(const float4*)(W + (size_t)(k0 + k) * ld + wc0 + n4 * 4);
            *(float4*)&Bs[k][n4 * 4] = w4;
        }
        __syncthreads();

        #pragma unroll
        for (int kk = 0; kk < 8; kk++) {
            float4 a0 = *(const float4*)&Xs[kk][ty * 4];
            float4 a1 = *(const float4*)&Xs[kk][64 + ty * 4];
            float4 b0 = *(const float4*)&Bs[kk][tx * 4];
            float4 b1 = *(const float4*)&Bs[kk][64 + tx * 4];
            unsigned long long bp[4] = {
                pack2(b0.x, b0.y), pack2(b0.z, b0.w),
                pack2(b1.x, b1.y), pack2(b1.z, b1.w)
            };
            float a[8] = { a0.x, a0.y, a0.z, a0.w, a1.x, a1.y, a1.z, a1.w };
            #pragma unroll
            for (int i = 0; i < 8; i++) {
                unsigned long long ap = pack2(a[i], a[i]);
                fma2(acc2[i][0], ap, bp[0]);
                fma2(acc2[i][1], ap, bp[1]);
                fma2(acc2[i][2], ap, bp[2]);
                fma2(acc2[i][3], ap, bp[3]);
            }
        }
        __syncthreads();
    }

    #pragma unroll
    for (int i = 0; i < 8; i++) {
        int r = row0 + ((i < 4) ? (ty * 4 + i) : (64 + ty * 4 + i - 4));
        #pragma unroll
        for (int j = 0; j < 4; j++) {
            int nb = (j < 2) ? (tx * 4 + j * 2) : (64 + tx * 4 + (j - 2) * 2);
            float lo, hi;
            unpack2(acc2[i][j], lo, hi);
            if (nb < nvalid)
                g_Z[(size_t)r * ZLD + col0 + nb] = lo + bias[wc0 + nb];
            if (nb + 1 < nvalid)
                g_Z[(size_t)r * ZLD + col0 + nb + 1] = hi + bias[wc0 + nb + 1];
        }
    }
}

__device__ __forceinline__ float sigmoidf_(float x) {
    return 1.f / (1.f + __expf(-x));
}

__device__ __forceinline__ void red_add_u64(unsigned long long* p) {
    asm volatile("red.global.gpu.add.u64 [%0], %1;" :: "l"(p), "l"(1ull) : "memory");
}
__device__ __forceinline__ unsigned long long ld_vol_u64(const unsigned long long* p) {
    unsigned long long v;
    asm volatile("ld.volatile.global.u64 %0, [%1];" : "=l"(v) : "l"(p));
    return v;
}

// ---------------------------------------------------------------------------
// Kernel 2: persistent recurrence — VERBATIM round-6 kernel (verified 7.84ms).
// 128 CTAs (4 b-tiles x 32 u-tiles), 512 threads.
// warp = (kch 0..7, rh 0..1); lane = (uu 0..7, kcl 0..3); kc = kch*4+kcl (8-k
// chunk). Weights (packed k-pairs) in registers; cx in owner registers.
// Per-group monotonic-counter barrier (self-calibrating base; replay-safe).
// ---------------------------------------------------------------------------
__global__ void __launch_bounds__(512, 1)
lstm_persistent(const float* __restrict__ Wf,
                const float* __restrict__ Wi,
                const float* __restrict__ Wg,
                const float* __restrict__ Wo,
                const float* __restrict__ Wq,
                float* __restrict__ stacked,   // [T,B,256]
                float* __restrict__ hx_out,    // [B,256]
                float* __restrict__ cx_out)    // [B,256]
{
    __shared__ float sm_h[16 * 264];        // hx tile, padded rows
    __shared__ float sm_red[16 * 352];      // [warp][uu(44)][c2*20+j*5+g]

    const int tid  = threadIdx.x;           // 512
    const int warp = tid >> 5;              // 0..15
    const int lane = tid & 31;
    const int b0   = blockIdx.x * 16;       // gridDim.x = 4
    const int u0   = blockIdx.y * 8;        // gridDim.y = 32

    const int uu   = lane & 7;
    const int kcl  = lane >> 3;             // 0..3
    const int kch  = warp & 7;              // 0..7
    const int rh   = warp >> 3;             // 0..1
    const int k0   = (kch * 4 + kcl) * 8;   // 8-k chunk base

    // ---- weights: packed k-pairs, 5 gates x 4 pairs, in registers ----
    unsigned long long wv[5][4];
    {
        const float* Wp[4] = { Wf, Wi, Wg, Wo };
        #pragma unroll
        for (int g = 0; g < 4; g++)
            #pragma unroll
            for (int kp = 0; kp < 4; kp++) {
                int k = 256 + k0 + 2 * kp;
                wv[g][kp] = pack2(Wp[g][(size_t)k * 256 + u0 + uu],
                                  Wp[g][(size_t)(k + 1) * 256 + u0 + uu]);
            }
        #pragma unroll
        for (int kp = 0; kp < 4; kp++) {
            int k = 256 + k0 + 2 * kp;
            wv[4][kp] = pack2(Wq[(size_t)k * 8 + uu], Wq[(size_t)(k + 1) * 8 + uu]);
        }
    }

    // ---- owner mapping: tid < 128 -> one (row, unit) output ----
    const int o_row = tid >> 3;
    const int o_uu  = tid & 7;
    const int ob    = b0 + o_row;
    const int oug   = u0 + o_uu;
    const float* o_z = g_Z + (size_t)ob * ZLD;
    float c = 0.f, h = 0.f;

    unsigned long long* ctr = &g_ctr[blockIdx.x * 16];
    unsigned long long base = 0ull;         // thread0 only

    for (int t = 0; t < T_STEPS; t++) {
        // prefetch Z (independent of recurrence) before the wait
        float zF = 0.f, zI = 0.f, zG = 0.f, zO = 0.f, zQ = 0.f;
        if (tid < 128) {
            const float* z = o_z + (size_t)t * BATCH * ZLD;
            zF = __ldg(z + oug);
            zI = __ldg(z + 256 + oug);
            zG = __ldg(z + 512 + oug);
            zO = __ldg(z + 768 + oug);
            zQ = __ldg(z + 1024 + o_uu);
        }

        // ---- wait for step t-1 of this b-tile group ----
        if (t > 0) {
            if (tid == 0) {
                unsigned long long target = base + (unsigned long long)t * GRP_CTAS;
                while (ld_vol_u64(ctr) < target)
                    __nanosleep(16);
            }
            __syncthreads();
        }

        // ---- stage hx tile (stacked[t-1], zeros at t==0) ----
        const float4* hsrc = (const float4*)(stacked + ((size_t)(t - 1) * BATCH + b0) * 256);
        #pragma unroll
        for (int i = 0; i < 2; i++) {
            int idx = tid + i * 512;            // 0..1023
            int row = idx >> 6, k4 = idx & 63;
            float4 v;
            if (t == 0) { v.x = v.y = v.z = v.w = 0.f; }
            else        { v = __ldcg(hsrc + (size_t)row * 64 + k4); }
            *(float4*)(sm_h + row * 264 + k4 * 4) = v;
        }
        __syncthreads();

        // ---- two 4-row passes: dots + reduce ----
        #pragma unroll
        for (int c2 = 0; c2 < 2; c2++) {
            unsigned long long acc[4][5];
            #pragma unroll
            for (int j = 0; j < 4; j++)
                #pragma unroll
                for (int g = 0; g < 5; g++) acc[j][g] = 0ull;

            #pragma unroll
            for (int j = 0; j < 4; j++) {
                const float* hrow = sm_h + (rh * 8 + c2 * 4 + j) * 264 + k0;
                float4 hv0 = *(const float4*)(hrow);
                float4 hv1 = *(const float4*)(hrow + 4);
                unsigned long long hk0 = pack2(hv0.x, hv0.y);
                unsigned long long hk1 = pack2(hv0.z, hv0.w);
                unsigned long long hk2 = pack2(hv1.x, hv1.y);
                unsigned long long hk3 = pack2(hv1.z, hv1.w);
                #pragma unroll
                for (int g = 0; g < 5; g++) {
                    fma2(acc[j][g], hk0, wv[g][0]);
                    fma2(acc[j][g], hk1, wv[g][1]);
                    fma2(acc[j][g], hk2, wv[g][2]);
                    fma2(acc[j][g], hk3, wv[g][3]);
                }
            }

            // horizontal + reduce over kcl (lane bits 3,4)
            float v[20];
            #pragma unroll
            for (int j = 0; j < 4; j++)
                #pragma unroll
                for (int g = 0; g < 5; g++) {
                    float lo, hi;
                    unpack2(acc[j][g], lo, hi);
                    v[j * 5 + g] = lo + hi;
                }
            #pragma unroll
            for (int m = 0; m < 20; m++) {
                v[m] += __shfl_xor_sync(0xffffffffu, v[m], 8);
                v[m] += __shfl_xor_sync(0xffffffffu, v[m], 16);
            }
            if (kcl == 0) {
                float* dst = sm_red + warp * 352 + uu * 44 + c2 * 20;
                #pragma unroll
                for (int q4 = 0; q4 < 5; q4++)
                    *(float4*)(dst + q4 * 4) = make_float4(v[q4*4], v[q4*4+1],
                                                           v[q4*4+2], v[q4*4+3]);
            }
        }
        __syncthreads();

        // ---- owners finalize ----
        if (tid < 128) {
            const int rh_o = o_row >> 3;
            const int rr   = o_row & 7;
            const int c2_o = rr >> 2;
            const int j_o  = rr & 3;
            float aF = zF, aI = zI, aG = zG, aO = zO, aQ = zQ;
            #pragma unroll
            for (int w2 = 0; w2 < 8; w2++) {
                const float* src = sm_red + (rh_o * 8 + w2) * 352 + o_uu * 44
                                 + c2_o * 20 + j_o * 5;
                aF += src[0]; aI += src[1]; aG += src[2]; aO += src[3]; aQ += src[4];
            }

            float s = tanhf(aQ);
            s += __shfl_xor_sync(0xffffffffu, s, 1);
            s += __shfl_xor_sync(0xffffffffu, s, 2);
            s += __shfl_xor_sync(0xffffffffu, s, 4);
            const float qout = sigmoidf_(s);

            const float f = (1.f - QSTR) * sigmoidf_(aF) + QSTR * qout;
            const float i = sigmoidf_(aI);
            const float g = tanhf(aG);
            const float o = sigmoidf_(aO);

            c = f * c + i * g;
            h = o * tanhf(c);

            __stcg(stacked + ((size_t)t * BATCH + ob) * 256 + oug, h);
            __threadfence();   // h visible before the arrive below
        }
        __syncthreads();

        // ---- arrive ----
        if (tid == 0) {
            if (t == 0) {
                unsigned long long a = atomicAdd(ctr, 1ull);
                base = (a / GRP_CTAS) * GRP_CTAS;   // counter base this launch
            } else {
                red_add_u64(ctr);
            }
        }
    }

    if (tid < 128) {
        hx_out[ob * 256 + oug] = h;
        cx_out[ob * 256 + oug] = c;
    }
}

// ---------------------------------------------------------------------------
extern "C" void kernel_launch(void* const* d_in, const int* in_sizes, int n_in,
                              void* d_out, int out_size)
{
    const float* X  = (const float*)d_in[0];
    const float* Wf = (const float*)d_in[1];
    const float* bf = (const float*)d_in[2];
    const float* Wi = (const float*)d_in[3];
    const float* bi = (const float*)d_in[4];
    const float* Wg = (const float*)d_in[5];
    const float* bg = (const float*)d_in[6];
    const float* Wo = (const float*)d_in[7];
    const float* bo = (const float*)d_in[8];
    const float* Wq = (const float*)d_in[9];
    const float* bq = (const float*)d_in[10];

    float* out     = (float*)d_out;
    float* stacked = out;                                  // [T,B,256]
    float* hx_out  = out + (size_t)T_STEPS * BATCH * D_H;  // [B,256]
    float* cx_out  = hx_out + BATCH * D_H;                 // [B,256]

    // 1) precompute input projections (packed FFMA2 GEMM)
    dim3 g1(T_STEPS * BATCH / 128, 9);
    xproj_kernel<<<g1, 256>>>(X, Wf, bf, Wi, bi, Wg, bg, Wo, bo, Wq, bq);

    // 2) persistent recurrence (verified R6 kernel)
    dim3 g2(4, 32);
    lstm_persistent<<<g2, 512>>>(Wf, Wi, Wg, Wo, Wq, stacked, hx_out, cx_out);
}